// round 1
// baseline (speedup 1.0000x reference)
#include <cuda_runtime.h>
#include <cstdint>

// ---------------- problem constants ----------------
#define L_LEVELS 16
#define T_SIZE   32768
#define TMASK    32767u
#define P1 2654435761u
#define P2 805459861u
#define BLOCK2 128
#define MAXN (1 << 20)

// scratch: compacted active points (no cudaMalloc allowed)
__device__ float4 g_pts[MAXN];
__device__ int    g_count;

// ---------------- kernel 1: mask + defaults + compaction ----------------
__global__ void k_mask_compact(const float* __restrict__ xyz,
                               const float* __restrict__ bmin,
                               const float* __restrict__ bmax,
                               float* __restrict__ out, int N)
{
    int i = blockIdx.x * blockDim.x + threadIdx.x;
    bool valid = (i < N);
    bool inb = false;
    float cx = 0.f, cy = 0.f, cz = 0.f;

    if (valid) {
        float bx0 = bmin[0], by0 = bmin[1], bz0 = bmin[2];
        float bx1 = bmax[0], by1 = bmax[1], bz1 = bmax[2];
        float x = xyz[3 * i + 0];
        float y = xyz[3 * i + 1];
        float z = xyz[3 * i + 2];
        cx = (x - bx0) / (bx1 - bx0);
        cy = (y - by0) / (by1 - by0);
        cz = (z - bz0) / (bz1 - bz0);
        inb = (cx >= 0.f) & (cx <= 1.f) &
              (cy >= 0.f) & (cy <= 1.f) &
              (cz >= 0.f) & (cz <= 1.f);

        // outputs: [mask N][d_xyz 3N][d_rot 4N], all f32
        out[i] = inb ? 1.f : 0.f;
        float* dxyz = out + N;
        float* drot = out + (size_t)4 * N;
        dxyz[3 * i + 0] = 0.f;
        dxyz[3 * i + 1] = 0.f;
        dxyz[3 * i + 2] = 0.f;
        drot[4 * i + 0] = 1.f;  // identity quaternion default
        drot[4 * i + 1] = 0.f;
        drot[4 * i + 2] = 0.f;
        drot[4 * i + 3] = 0.f;
    }

    // warp-aggregated compaction of active points
    unsigned m = __ballot_sync(0xffffffffu, inb);
    if (inb) {
        int lane = threadIdx.x & 31;
        int leader = __ffs(m) - 1;
        int base = 0;
        if (lane == leader) base = atomicAdd(&g_count, __popc(m));
        base = __shfl_sync(m, base, leader);
        int slot = base + __popc(m & ((1u << lane) - 1u));
        // clamp (no-op for in-bounds, matches reference clip)
        cx = fminf(fmaxf(cx, 0.f), 1.f);
        cy = fminf(fmaxf(cy, 0.f), 1.f);
        cz = fminf(fmaxf(cz, 0.f), 1.f);
        g_pts[slot] = make_float4(cx, cy, cz, __int_as_float(i));
    }
}

// ---------------- kernel 2: hash encode + MLP (active points only) -------
// smem: [w0 4096][w1 4096][w2 512][act 64*BLOCK2]
__global__ __launch_bounds__(BLOCK2, 3)
void k_encode_mlp(const float* __restrict__ table,
                  const float* __restrict__ w0,
                  const float* __restrict__ w1,
                  const float* __restrict__ w2,
                  float* __restrict__ out, int N)
{
    extern __shared__ float sm[];
    float* sw0  = sm;            // 4096 floats
    float* sw1  = sm + 4096;     // 4096 floats
    float* sw2  = sm + 8192;     // 512 floats
    float* sact = sm + 8704;     // 64 * BLOCK2 floats

    int tid = threadIdx.x;
    int cnt = g_count;
    if ((int)(blockIdx.x * BLOCK2) >= cnt) return;  // uniform per block

    // stage weights in smem (vectorized)
    for (int k = tid; k < 4096 / 4; k += BLOCK2)
        ((float4*)sw0)[k] = ((const float4*)w0)[k];
    for (int k = tid; k < 4096 / 4; k += BLOCK2)
        ((float4*)sw1)[k] = ((const float4*)w1)[k];
    for (int k = tid; k < 512 / 4; k += BLOCK2)
        ((float4*)sw2)[k] = ((const float4*)w2)[k];
    __syncthreads();

    const float4* tbl = (const float4*)table;
    float* dxyz = out + N;
    float* drot = out + (size_t)4 * N;

    for (int slot = blockIdx.x * BLOCK2 + tid; slot < cnt;
         slot += gridDim.x * BLOCK2) {
        float4 p = g_pts[slot];
        float cx = p.x, cy = p.y, cz = p.z;
        int ipt = __float_as_int(p.w);

        // h0 accumulator (layer-1 output, pre-relu), fused with encode
        float h[64];
        #pragma unroll
        for (int j = 0; j < 64; j++) h[j] = 0.f;

        float sc = 16.f;
        #pragma unroll 1
        for (int l = 0; l < L_LEVELS; l++) {
            float px = cx * sc, py = cy * sc, pz = cz * sc;
            float fx = floorf(px), fy = floorf(py), fz = floorf(pz);
            float tx = px - fx, ty = py - fy, tz = pz - fz;
            unsigned ux = (unsigned)fx, uy = (unsigned)fy, uz = (unsigned)fz;

            unsigned hx0 = ux,        hx1 = ux + 1u;
            unsigned hy0 = uy * P1,   hy1 = hy0 + P1;
            unsigned hz0 = uz * P2,   hz1 = hz0 + P2;
            unsigned base = (unsigned)l * T_SIZE;

            float wx[2] = {1.f - tx, tx};
            float wy[2] = {1.f - ty, ty};
            float wz[2] = {1.f - tz, tz};

            float a0 = 0.f, a1 = 0.f, a2 = 0.f, a3 = 0.f;
            #pragma unroll
            for (int c = 0; c < 8; c++) {
                unsigned hx = (c & 4) ? hx1 : hx0;
                unsigned hy = (c & 2) ? hy1 : hy0;
                unsigned hz = (c & 1) ? hz1 : hz0;
                unsigned idx = (hx ^ hy ^ hz) & TMASK;
                float4 f = __ldg(tbl + (base + idx));
                float w = wx[(c >> 2) & 1] * wy[(c >> 1) & 1] * wz[c & 1];
                a0 += w * f.x; a1 += w * f.y; a2 += w * f.z; a3 += w * f.w;
            }

            // accumulate this level's 4 enc features into h0
            float av[4] = {a0, a1, a2, a3};
            #pragma unroll
            for (int f = 0; f < 4; f++) {
                const float4* wr = (const float4*)(sw0 + ((l * 4 + f) << 6));
                float a = av[f];
                #pragma unroll
                for (int jj = 0; jj < 16; jj++) {
                    float4 wv = wr[jj];
                    h[4 * jj + 0] += a * wv.x;
                    h[4 * jj + 1] += a * wv.y;
                    h[4 * jj + 2] += a * wv.z;
                    h[4 * jj + 3] += a * wv.w;
                }
            }
            sc *= 2.f;
        }

        // relu(h0) -> smem spill lane (per-thread private column)
        #pragma unroll
        for (int j = 0; j < 64; j++)
            sact[j * BLOCK2 + tid] = fmaxf(h[j], 0.f);

        // layer 2: h1 = relu(h0r @ w1)
        #pragma unroll
        for (int j = 0; j < 64; j++) h[j] = 0.f;
        #pragma unroll 4
        for (int i = 0; i < 64; i++) {
            float v = sact[i * BLOCK2 + tid];
            const float4* wr = (const float4*)(sw1 + (i << 6));
            #pragma unroll
            for (int jj = 0; jj < 16; jj++) {
                float4 wv = wr[jj];
                h[4 * jj + 0] += v * wv.x;
                h[4 * jj + 1] += v * wv.y;
                h[4 * jj + 2] += v * wv.z;
                h[4 * jj + 3] += v * wv.w;
            }
        }
        #pragma unroll
        for (int j = 0; j < 64; j++)
            sact[j * BLOCK2 + tid] = fmaxf(h[j], 0.f);

        // layer 3: resi = h1r @ w2  (8 outputs)
        float o[8];
        #pragma unroll
        for (int k = 0; k < 8; k++) o[k] = 0.f;
        #pragma unroll 8
        for (int i = 0; i < 64; i++) {
            float v = sact[i * BLOCK2 + tid];
            const float4* wr = (const float4*)(sw2 + (i << 3));
            float4 wa = wr[0], wb = wr[1];
            o[0] += v * wa.x; o[1] += v * wa.y; o[2] += v * wa.z; o[3] += v * wa.w;
            o[4] += v * wb.x; o[5] += v * wb.y; o[6] += v * wb.z; o[7] += v * wb.w;
        }

        dxyz[3 * ipt + 0] = o[0];
        dxyz[3 * ipt + 1] = o[1];
        dxyz[3 * ipt + 2] = o[2];
        drot[4 * ipt + 0] = o[3];
        drot[4 * ipt + 1] = o[4];
        drot[4 * ipt + 2] = o[5];
        drot[4 * ipt + 3] = o[6];
    }
}

// ---------------- launch ----------------
extern "C" void kernel_launch(void* const* d_in, const int* in_sizes, int n_in,
                              void* d_out, int out_size)
{
    const float* xyz   = (const float*)d_in[0];
    const float* bmin  = (const float*)d_in[1];
    const float* bmax  = (const float*)d_in[2];
    const float* table = (const float*)d_in[3];
    const float* w0    = (const float*)d_in[4];
    const float* w1    = (const float*)d_in[5];
    const float* w2    = (const float*)d_in[6];
    int N = in_sizes[0] / 3;
    float* out = (float*)d_out;

    void* cptr = nullptr;
    cudaGetSymbolAddress(&cptr, g_count);
    cudaMemsetAsync(cptr, 0, sizeof(int), 0);

    int grid1 = (N + 255) / 256;
    k_mask_compact<<<grid1, 256>>>(xyz, bmin, bmax, out, N);

    int smem = (8704 + 64 * BLOCK2) * (int)sizeof(float);  // 67584 B
    cudaFuncSetAttribute(k_encode_mlp,
                         cudaFuncAttributeMaxDynamicSharedMemorySize, smem);
    int grid2 = 444;  // ~3 blocks/SM resident, grid-stride over compacted pts
    k_encode_mlp<<<grid2, BLOCK2, smem>>>(table, w0, w1, w2, out, N);
}